// round 1
// baseline (speedup 1.0000x reference)
#include <cuda_runtime.h>
#include <math.h>

// Problem constants
#define B_   8
#define L_   768
#define H_   16
#define DK_  64
#define D_   1024
#define BH_  (B_ * H_)          // 128
#define M_   (B_ * L_)          // 6144
#define SCALE 0.125f            // 1/sqrt(64)

// Scratch (device globals -- no allocation allowed)
__device__ float g_Qp[BH_ * L_ * DK_];   // [bh][l][d]
__device__ float g_Kp[BH_ * L_ * DK_];
__device__ float g_Vp[BH_ * L_ * DK_];
__device__ float g_S [(size_t)BH_ * L_ * L_];  // scores / probs, 302MB
__device__ float g_O [BH_ * L_ * DK_];   // attention output per head

// ---------------------------------------------------------------------------
// Kernel 1: projection GEMM  out[b,h,l,d] = X[b*l,:] @ W[h*64+d,:] + bias
// X: [6144,1024] row-major, W: [1024,1024] row-major (torch Linear weight)
// 64x64 tile, BK=16, 256 threads, 4x4 per thread
// ---------------------------------------------------------------------------
__global__ __launch_bounds__(256)
void proj_kernel(const float* __restrict__ X, const float* __restrict__ W,
                 const float* __restrict__ bias, float* __restrict__ OUT)
{
    __shared__ __align__(16) float As[16][68];
    __shared__ __align__(16) float Bs[16][68];
    const int t  = threadIdx.x;
    const int tx = t & 15, ty = t >> 4;
    const int m0 = blockIdx.y * 64, n0 = blockIdx.x * 64;
    const int mload = t >> 2, kload = (t & 3) * 4;

    float acc[4][4] = {};
    for (int kt = 0; kt < 1024; kt += 16) {
        float4 av = *(const float4*)&X[(size_t)(m0 + mload) * 1024 + kt + kload];
        float4 bv = *(const float4*)&W[(size_t)(n0 + mload) * 1024 + kt + kload];
        As[kload+0][mload] = av.x; As[kload+1][mload] = av.y;
        As[kload+2][mload] = av.z; As[kload+3][mload] = av.w;
        Bs[kload+0][mload] = bv.x; Bs[kload+1][mload] = bv.y;
        Bs[kload+2][mload] = bv.z; Bs[kload+3][mload] = bv.w;
        __syncthreads();
#pragma unroll
        for (int kk = 0; kk < 16; kk++) {
            float4 a4 = *(const float4*)&As[kk][ty * 4];
            float4 b4 = *(const float4*)&Bs[kk][tx * 4];
            float a[4] = {a4.x, a4.y, a4.z, a4.w};
            float b[4] = {b4.x, b4.y, b4.z, b4.w};
#pragma unroll
            for (int i = 0; i < 4; i++)
#pragma unroll
                for (int j = 0; j < 4; j++)
                    acc[i][j] = fmaf(a[i], b[j], acc[i][j]);
        }
        __syncthreads();
    }
#pragma unroll
    for (int i = 0; i < 4; i++) {
        int m = m0 + ty * 4 + i;
        int bb = m / 768, l = m - bb * 768;
#pragma unroll
        for (int j = 0; j < 4; j++) {
            int n = n0 + tx * 4 + j;
            int h = n >> 6, d = n & 63;
            OUT[(((size_t)(bb * 16 + h) * 768) + l) * 64 + d] = acc[i][j] + bias[n];
        }
    }
}

// ---------------------------------------------------------------------------
// Kernel 2: scores with fused relative-position bias.
// S[bh,q,k] = SCALE * ( Q[q,:]·K[k,:] + Q[q,:]·E[k-q+767,:] )
// Per block: (k-tile bx, q-tile by, bh bz). Stage 1 builds the 64x128
// rel-window Rs = Qtile @ E_window^T in smem; stage 2 does QK^T.
// ---------------------------------------------------------------------------
__global__ __launch_bounds__(256)
void scores_kernel(const float* __restrict__ E)
{
    __shared__ __align__(16) float As[16][68];
    __shared__ __align__(16) float Bs[16][68];
    __shared__ float Rs[64][129];

    const int t  = threadIdx.x;
    const int tx = t & 15, ty = t >> 4;
    const int bh = blockIdx.z;
    const int q0 = blockIdx.y * 64, k0 = blockIdx.x * 64;
    const float* Q = g_Qp + (size_t)bh * L_ * DK_;
    const float* K = g_Kp + (size_t)bh * L_ * DK_;
    const int mload = t >> 2, kload = (t & 3) * 4;
    const int jbase = k0 - q0 + 704;  // = k0-q0+767-63, in [0,1408]

    // ---- stage 1: Rs[qi][r] = sum_d Q[q0+qi][d] * E[jbase+r][d], r in 0..127
    for (int half = 0; half < 2; half++) {
        float acc[4][4] = {};
        for (int kt = 0; kt < 64; kt += 16) {
            float4 av = *(const float4*)&Q[(size_t)(q0 + mload) * 64 + kt + kload];
            int erow = jbase + half * 64 + mload;
            float4 bv = (erow <= 1534)
                ? *(const float4*)&E[(size_t)erow * 64 + kt + kload]
                : make_float4(0.f, 0.f, 0.f, 0.f);
            As[kload+0][mload] = av.x; As[kload+1][mload] = av.y;
            As[kload+2][mload] = av.z; As[kload+3][mload] = av.w;
            Bs[kload+0][mload] = bv.x; Bs[kload+1][mload] = bv.y;
            Bs[kload+2][mload] = bv.z; Bs[kload+3][mload] = bv.w;
            __syncthreads();
#pragma unroll
            for (int kk = 0; kk < 16; kk++) {
                float4 a4 = *(const float4*)&As[kk][ty * 4];
                float4 b4 = *(const float4*)&Bs[kk][tx * 4];
                float a[4] = {a4.x, a4.y, a4.z, a4.w};
                float b[4] = {b4.x, b4.y, b4.z, b4.w};
#pragma unroll
                for (int i = 0; i < 4; i++)
#pragma unroll
                    for (int j = 0; j < 4; j++)
                        acc[i][j] = fmaf(a[i], b[j], acc[i][j]);
            }
            __syncthreads();
        }
#pragma unroll
        for (int i = 0; i < 4; i++)
#pragma unroll
            for (int j = 0; j < 4; j++)
                Rs[ty * 4 + i][half * 64 + tx * 4 + j] = acc[i][j];
    }
    __syncthreads();

    // ---- stage 2: QK^T
    float acc[4][4] = {};
    for (int kt = 0; kt < 64; kt += 16) {
        float4 av = *(const float4*)&Q[(size_t)(q0 + mload) * 64 + kt + kload];
        float4 bv = *(const float4*)&K[(size_t)(k0 + mload) * 64 + kt + kload];
        As[kload+0][mload] = av.x; As[kload+1][mload] = av.y;
        As[kload+2][mload] = av.z; As[kload+3][mload] = av.w;
        Bs[kload+0][mload] = bv.x; Bs[kload+1][mload] = bv.y;
        Bs[kload+2][mload] = bv.z; Bs[kload+3][mload] = bv.w;
        __syncthreads();
#pragma unroll
        for (int kk = 0; kk < 16; kk++) {
            float4 a4 = *(const float4*)&As[kk][ty * 4];
            float4 b4 = *(const float4*)&Bs[kk][tx * 4];
            float a[4] = {a4.x, a4.y, a4.z, a4.w};
            float b[4] = {b4.x, b4.y, b4.z, b4.w};
#pragma unroll
            for (int i = 0; i < 4; i++)
#pragma unroll
                for (int j = 0; j < 4; j++)
                    acc[i][j] = fmaf(a[i], b[j], acc[i][j]);
        }
        __syncthreads();
    }
    float* Srow = g_S + (size_t)bh * L_ * L_;
#pragma unroll
    for (int i = 0; i < 4; i++) {
        int qi = ty * 4 + i;
#pragma unroll
        for (int j = 0; j < 4; j++) {
            int ki = tx * 4 + j;
            float v = SCALE * (acc[i][j] + Rs[qi][ki - qi + 63]);
            Srow[(size_t)(q0 + qi) * L_ + (k0 + ki)] = v;
        }
    }
}

// ---------------------------------------------------------------------------
// Kernel 3: row softmax over k (row length 768), in-place on g_S.
// One block (256 threads) per row; 3 elements per thread.
// ---------------------------------------------------------------------------
__global__ __launch_bounds__(256)
void softmax_kernel()
{
    float* p = g_S + (size_t)blockIdx.x * L_;
    const int t = threadIdx.x;
    float v0 = p[t], v1 = p[t + 256], v2 = p[t + 512];

    __shared__ float sred[8];
    __shared__ float sbcast;

    float m = fmaxf(v0, fmaxf(v1, v2));
#pragma unroll
    for (int o = 16; o; o >>= 1) m = fmaxf(m, __shfl_xor_sync(0xffffffffu, m, o));
    if ((t & 31) == 0) sred[t >> 5] = m;
    __syncthreads();
    if (t == 0) {
        float mm = sred[0];
#pragma unroll
        for (int w = 1; w < 8; w++) mm = fmaxf(mm, sred[w]);
        sbcast = mm;
    }
    __syncthreads();
    m = sbcast;

    float e0 = __expf(v0 - m), e1 = __expf(v1 - m), e2 = __expf(v2 - m);
    float s = e0 + e1 + e2;
#pragma unroll
    for (int o = 16; o; o >>= 1) s += __shfl_xor_sync(0xffffffffu, s, o);
    if ((t & 31) == 0) sred[t >> 5] = s;
    __syncthreads();
    if (t == 0) {
        float ss = sred[0];
#pragma unroll
        for (int w = 1; w < 8; w++) ss += sred[w];
        sbcast = 1.0f / ss;
    }
    __syncthreads();
    float inv = sbcast;
    p[t] = e0 * inv; p[t + 256] = e1 * inv; p[t + 512] = e2 * inv;
}

// ---------------------------------------------------------------------------
// Kernel 4: O[bh,q,d] = sum_k P[bh,q,k] * V[bh,k,d].  M=768,N=64,K=768.
// Grid: (1, 12 q-tiles, 128 bh). N=64 covered by one tile.
// ---------------------------------------------------------------------------
__global__ __launch_bounds__(256)
void av_kernel()
{
    __shared__ __align__(16) float As[16][68];
    __shared__ __align__(16) float Bs[16][68];
    const int t  = threadIdx.x;
    const int tx = t & 15, ty = t >> 4;
    const int bh = blockIdx.z;
    const int q0 = blockIdx.y * 64;
    const float* P = g_S + (size_t)bh * L_ * L_;
    const float* V = g_Vp + (size_t)bh * L_ * DK_;
    const int mload = t >> 2, kload = (t & 3) * 4;
    const int r = t >> 4, c4 = (t & 15) * 4;

    float acc[4][4] = {};
    for (int kt = 0; kt < 768; kt += 16) {
        float4 av = *(const float4*)&P[(size_t)(q0 + mload) * 768 + kt + kload];
        As[kload+0][mload] = av.x; As[kload+1][mload] = av.y;
        As[kload+2][mload] = av.z; As[kload+3][mload] = av.w;
        *(float4*)&Bs[r][c4] = *(const float4*)&V[(size_t)(kt + r) * 64 + c4];
        __syncthreads();
#pragma unroll
        for (int kk = 0; kk < 16; kk++) {
            float4 a4 = *(const float4*)&As[kk][ty * 4];
            float4 b4 = *(const float4*)&Bs[kk][tx * 4];
            float a[4] = {a4.x, a4.y, a4.z, a4.w};
            float b[4] = {b4.x, b4.y, b4.z, b4.w};
#pragma unroll
            for (int i = 0; i < 4; i++)
#pragma unroll
                for (int j = 0; j < 4; j++)
                    acc[i][j] = fmaf(a[i], b[j], acc[i][j]);
        }
        __syncthreads();
    }
#pragma unroll
    for (int i = 0; i < 4; i++) {
        int q = q0 + ty * 4 + i;
#pragma unroll
        for (int j = 0; j < 4; j++) {
            int d = tx * 4 + j;
            g_O[((size_t)bh * 768 + q) * 64 + d] = acc[i][j];
        }
    }
}

// ---------------------------------------------------------------------------
// Kernel 5: output projection. A gathered from g_O (merge heads),
// out[m,n] = A[m,:] @ Wo[n,:] + bo[n]
// ---------------------------------------------------------------------------
__global__ __launch_bounds__(256)
void oproj_kernel(const float* __restrict__ Wo, const float* __restrict__ bo,
                  float* __restrict__ out)
{
    __shared__ __align__(16) float As[16][68];
    __shared__ __align__(16) float Bs[16][68];
    const int t  = threadIdx.x;
    const int tx = t & 15, ty = t >> 4;
    const int m0 = blockIdx.y * 64, n0 = blockIdx.x * 64;
    const int mload = t >> 2, kload = (t & 3) * 4;

    const int mrow = m0 + mload;
    const int bb = mrow / 768, l = mrow - bb * 768;

    float acc[4][4] = {};
    for (int kt = 0; kt < 1024; kt += 16) {
        int kg = kt + kload;
        int h = kg >> 6, d = kg & 63;
        float4 av = *(const float4*)&g_O[(((size_t)(bb * 16 + h) * 768) + l) * 64 + d];
        float4 bv = *(const float4*)&Wo[(size_t)(n0 + mload) * 1024 + kt + kload];
        As[kload+0][mload] = av.x; As[kload+1][mload] = av.y;
        As[kload+2][mload] = av.z; As[kload+3][mload] = av.w;
        Bs[kload+0][mload] = bv.x; Bs[kload+1][mload] = bv.y;
        Bs[kload+2][mload] = bv.z; Bs[kload+3][mload] = bv.w;
        __syncthreads();
#pragma unroll
        for (int kk = 0; kk < 16; kk++) {
            float4 a4 = *(const float4*)&As[kk][ty * 4];
            float4 b4 = *(const float4*)&Bs[kk][tx * 4];
            float a[4] = {a4.x, a4.y, a4.z, a4.w};
            float b[4] = {b4.x, b4.y, b4.z, b4.w};
#pragma unroll
            for (int i = 0; i < 4; i++)
#pragma unroll
                for (int j = 0; j < 4; j++)
                    acc[i][j] = fmaf(a[i], b[j], acc[i][j]);
        }
        __syncthreads();
    }
#pragma unroll
    for (int i = 0; i < 4; i++) {
        int m = m0 + ty * 4 + i;
#pragma unroll
        for (int j = 0; j < 4; j++) {
            int n = n0 + tx * 4 + j;
            out[(size_t)m * 1024 + n] = acc[i][j] + bo[n];
        }
    }
}

// ---------------------------------------------------------------------------
extern "C" void kernel_launch(void* const* d_in, const int* in_sizes, int n_in,
                              void* d_out, int out_size)
{
    const float* query = (const float*)d_in[0];
    const float* key   = (const float*)d_in[1];
    const float* value = (const float*)d_in[2];
    const float* w_q   = (const float*)d_in[3];
    const float* b_q   = (const float*)d_in[4];
    const float* w_k   = (const float*)d_in[5];
    const float* b_k   = (const float*)d_in[6];
    const float* w_v   = (const float*)d_in[7];
    const float* b_v   = (const float*)d_in[8];
    const float* w_o   = (const float*)d_in[9];
    const float* b_o   = (const float*)d_in[10];
    const float* relE  = (const float*)d_in[11];
    float* out = (float*)d_out;

    // device global pointers resolved via symbol lookup inside kernels (they
    // reference the globals directly); here we need addresses only for proj
    float* qp; float* kp; float* vp;
    cudaGetSymbolAddress((void**)&qp, g_Qp);
    cudaGetSymbolAddress((void**)&kp, g_Kp);
    cudaGetSymbolAddress((void**)&vp, g_Vp);

    dim3 gproj(16, 96);
    proj_kernel<<<gproj, 256>>>(query, w_q, b_q, qp);
    proj_kernel<<<gproj, 256>>>(key,   w_k, b_k, kp);
    proj_kernel<<<gproj, 256>>>(value, w_v, b_v, vp);

    scores_kernel<<<dim3(12, 12, 128), 256>>>(relE);
    softmax_kernel<<<BH_ * L_, 256>>>();
    av_kernel<<<dim3(1, 12, 128), 256>>>();
    oproj_kernel<<<dim3(16, 96), 256>>>(w_o, b_o, out);
}